// round 9
// baseline (speedup 1.0000x reference)
#include <cuda_runtime.h>
#include <cuda_bf16.h>
#include <cuda_fp16.h>

// Problem constants (EdgeConv_33930241638504): N=50000, E=800000, IN=OUT=16, T=8
#define MAXN 50048
#define IN_F 16
#define OUT_F 16
#define T_F 8
#define LN_EPS 1e-5f

// h table: fp16 [n][16] (1.6 MB, L2-resident; gathered 32B per edge)
__device__ __half g_h[(size_t)MAXN * 16];
__device__ int    g_idx64;   // 1 if edge_index int64, 0 if int32

// ---------------------------------------------------------------------------
// Kernel 1: per-node preprocessing (+ dtype detection).
// 16 lanes per node; lane = o. h = relu(LN(x)) -> g_h fp16;
// out[n,o] = sum_i h[i]*root[i,o] + bias[o]
// ---------------------------------------------------------------------------
#define OPAD 20
__global__ __launch_bounds__(256) void node_kernel(
    const float* __restrict__ x,
    const float* __restrict__ ln_gamma,
    const float* __restrict__ ln_beta,
    const float* __restrict__ root,     // [IN, OUT]
    const float* __restrict__ bias,     // [OUT]
    const unsigned int* __restrict__ idx_raw,
    float* __restrict__ out,
    int N)
{
    __shared__ float Rt[IN_F * OPAD];   // [o*20 + i]

    for (int idx = threadIdx.x; idx < IN_F * OUT_F; idx += blockDim.x) {
        int i = idx >> 4, o = idx & 15;
        Rt[o * OPAD + i] = root[idx];
    }

    // dtype detection: int64 LE with values < N => odd 32-bit words all zero.
    if (blockIdx.x == 0 && threadIdx.x < 32) {
        int lane = threadIdx.x;
        unsigned int any = 0;
        #pragma unroll
        for (int k = 0; k < 8; k++) any |= idx_raw[2 * (lane * 8 + k) + 1];
        unsigned int ballot = __ballot_sync(0xffffffffu, any != 0);
        if (lane == 0) g_idx64 = (ballot == 0u) ? 1 : 0;
    }
    __syncthreads();

    int gtid = blockIdx.x * blockDim.x + threadIdx.x;
    int node = gtid >> 4;
    int o    = gtid & 15;
    bool valid = (node < N);
    int n = valid ? node : (N - 1);

    float xv = x[n * IN_F + o];

    float s = xv;
    #pragma unroll
    for (int off = 8; off > 0; off >>= 1) s += __shfl_xor_sync(0xffffffffu, s, off, 16);
    float mu = s * (1.0f / 16.0f);
    float d = xv - mu;
    float v = d * d;
    #pragma unroll
    for (int off = 8; off > 0; off >>= 1) v += __shfl_xor_sync(0xffffffffu, v, off, 16);
    float var = v * (1.0f / 16.0f);
    float rstd = rsqrtf(var + LN_EPS);

    float h_own = d * rstd * ln_gamma[o] + ln_beta[o];
    h_own = fmaxf(h_own, 0.0f);

    if (valid) g_h[(size_t)n * 16 + o] = __float2half(h_own);

    // out init: root transform + bias
    float4 h4[4];
    {
        float hv[IN_F];
        #pragma unroll
        for (int i = 0; i < IN_F; i++) hv[i] = __shfl_sync(0xffffffffu, h_own, i, 16);
        #pragma unroll
        for (int k = 0; k < 4; k++) h4[k] = make_float4(hv[4*k], hv[4*k+1], hv[4*k+2], hv[4*k+3]);
    }
    const float4* rrow = (const float4*)&Rt[o * OPAD];
    float acc = bias[o];
    #pragma unroll
    for (int k = 0; k < 4; k++) {
        float4 w = rrow[k];
        acc = fmaf(h4[k].x, w.x, acc);
        acc = fmaf(h4[k].y, w.y, acc);
        acc = fmaf(h4[k].z, w.z, acc);
        acc = fmaf(h4[k].w, w.w, acc);
    }
    if (valid) out[n * OUT_F + o] = acc;
}

// ---------------------------------------------------------------------------
// Kernel 2: tensor-core edge kernel.
// msg[16 edges, 16 outs] = phi[16,144] @ W2[144,16] via 9x2 mma.m16n8k16.
// phi[e, t*16+i] = ea[e,t]*h[src,i] (t<8), = h[src,i] (t==8, bias rows).
// Each warp: 2 groups of 16 edges. Epilogue: red.global.add.v2.f32.
// ---------------------------------------------------------------------------
__device__ __forceinline__ void mma16816(float* c, const unsigned* a, const unsigned* b)
{
    asm volatile("mma.sync.aligned.m16n8k16.row.col.f32.f16.f16.f32 "
                 "{%0,%1,%2,%3}, {%4,%5,%6,%7}, {%8,%9}, {%0,%1,%2,%3};"
                 : "+f"(c[0]), "+f"(c[1]), "+f"(c[2]), "+f"(c[3])
                 : "r"(a[0]), "r"(a[1]), "r"(a[2]), "r"(a[3]),
                   "r"(b[0]), "r"(b[1]));
}

#define EB 256   // edges per block (8 warps x 2 groups x 16)
__global__ __launch_bounds__(256) void edge_kernel(
    const void* __restrict__ edge_index,   // [2, E] int64 OR int32
    const float* __restrict__ edge_attr,   // [E, 8]
    const float* __restrict__ w_edge,      // [T, IN*OUT]
    const float* __restrict__ b_edge,      // [IN*OUT]
    float* __restrict__ out,
    int E)
{
    // W2 transposed: W2T[o][k], k = t*16+i (t<8), 128+i (bias)
    __shared__ __half W2T[16 * 144];                     // 4.6 KB
    __shared__ alignas(16) float  eas[8][16][12];        // [warp][r][t] pad 12
    __shared__ alignas(16) __half hs[8][16][24];         // [warp][r][i] pad 24
    __shared__ int dsts[8][16];

    for (int idx = threadIdx.x; idx < 16 * 144; idx += blockDim.x) {
        int o = idx / 144, k = idx % 144;
        float v = (k < 128) ? w_edge[(k >> 4) * 256 + (k & 15) * 16 + o]
                            : b_edge[(k & 15) * 16 + o];
        W2T[o * 144 + k] = __float2half(v);
    }
    __syncthreads();

    int warp = threadIdx.x >> 5;
    int lane = threadIdx.x & 31;
    int grp  = lane >> 2;        // 0..7
    int tid  = lane & 3;         // 0..3
    int r0 = grp, r1 = grp + 8;

    // B fragments (constant): b[t][nt] = {rows tid*2,tid*2+1 | +8,+9; col nt*8+grp}
    unsigned bfrag[9][2][2];
    #pragma unroll
    for (int t = 0; t < 9; t++) {
        #pragma unroll
        for (int nt = 0; nt < 2; nt++) {
            int col = nt * 8 + grp;
            bfrag[t][nt][0] = *(const unsigned*)&W2T[col * 144 + t * 16 + tid * 2];
            bfrag[t][nt][1] = *(const unsigned*)&W2T[col * 144 + t * 16 + tid * 2 + 8];
        }
    }

    long base = (long)blockIdx.x * EB;

    #pragma unroll
    for (int it = 0; it < 2; it++) {
        long ebase = base + (warp * 2 + it) * 16;

        // load phase: lanes 0..15, one edge each
        if (lane < 16) {
            long e = ebase + lane;
            bool ev = (e < E);
            long ec = ev ? e : (E - 1);
            int s, dd;
            if (g_idx64) {
                const long long* ei = (const long long*)edge_index;
                s  = (int)ei[ec];
                dd = (int)ei[(long)E + ec];
            } else {
                const int* ei = (const int*)edge_index;
                s  = ei[ec];
                dd = ei[E + ec];
            }
            dsts[warp][lane] = ev ? dd : -1;
            const float4* ep = (const float4*)(edge_attr + ec * T_F);
            *(float4*)&eas[warp][lane][0] = ep[0];
            *(float4*)&eas[warp][lane][4] = ep[1];
            const uint4* hp = (const uint4*)(g_h + (size_t)s * 16);
            *(uint4*)&hs[warp][lane][0] = hp[0];
            *(uint4*)&hs[warp][lane][8] = hp[1];
        }
        __syncwarp();

        // h half2s for this thread's rows/cols (constant across k-steps)
        __half2 h00 = *(const __half2*)&hs[warp][r0][tid * 2];       // (r0, c0,c0+1)
        __half2 h10 = *(const __half2*)&hs[warp][r1][tid * 2];       // (r1, c0,c0+1)
        __half2 h01 = *(const __half2*)&hs[warp][r0][tid * 2 + 8];   // (r0, c0+8,+9)
        __half2 h11 = *(const __half2*)&hs[warp][r1][tid * 2 + 8];   // (r1, c0+8,+9)

        float acc0[4] = {0.f, 0.f, 0.f, 0.f};
        float acc1[4] = {0.f, 0.f, 0.f, 0.f};

        #pragma unroll
        for (int t = 0; t < 9; t++) {
            __half2 a0 = h00, a1 = h10, a2 = h01, a3 = h11;
            if (t < 8) {
                __half2 e0 = __float2half2_rn(eas[warp][r0][t]);
                __half2 e1 = __float2half2_rn(eas[warp][r1][t]);
                a0 = __hmul2(a0, e0);
                a1 = __hmul2(a1, e1);
                a2 = __hmul2(a2, e0);
                a3 = __hmul2(a3, e1);
            }
            unsigned a[4] = {*(unsigned*)&a0, *(unsigned*)&a1,
                             *(unsigned*)&a2, *(unsigned*)&a3};
            mma16816(acc0, a, bfrag[t][0]);
            mma16816(acc1, a, bfrag[t][1]);
        }

        // epilogue: acc{0,1}[0,1] -> row r0, cols nt*8+tid*2..+1 ; [2,3] -> row r1
        int d0 = dsts[warp][r0];
        int d1 = dsts[warp][r1];
        if (d0 >= 0) {
            float* p0 = out + (size_t)d0 * OUT_F + tid * 2;
            asm volatile("red.global.add.v2.f32 [%0], {%1, %2};"
                         :: "l"(p0), "f"(acc0[0]), "f"(acc0[1]) : "memory");
            float* p1 = out + (size_t)d0 * OUT_F + 8 + tid * 2;
            asm volatile("red.global.add.v2.f32 [%0], {%1, %2};"
                         :: "l"(p1), "f"(acc1[0]), "f"(acc1[1]) : "memory");
        }
        if (d1 >= 0) {
            float* p2 = out + (size_t)d1 * OUT_F + tid * 2;
            asm volatile("red.global.add.v2.f32 [%0], {%1, %2};"
                         :: "l"(p2), "f"(acc0[2]), "f"(acc0[3]) : "memory");
            float* p3 = out + (size_t)d1 * OUT_F + 8 + tid * 2;
            asm volatile("red.global.add.v2.f32 [%0], {%1, %2};"
                         :: "l"(p3), "f"(acc1[2]), "f"(acc1[3]) : "memory");
        }
        __syncwarp();   // protect smem before next group's overwrite
    }
}

// ---------------------------------------------------------------------------
extern "C" void kernel_launch(void* const* d_in, const int* in_sizes, int n_in,
                              void* d_out, int out_size)
{
    const float* x        = (const float*)d_in[0];
    const void*  eidx     = d_in[1];
    const float* eattr    = (const float*)d_in[2];
    const float* ln_gamma = (const float*)d_in[3];
    const float* ln_beta  = (const float*)d_in[4];
    const float* w_edge   = (const float*)d_in[5];
    const float* b_edge   = (const float*)d_in[6];
    const float* root     = (const float*)d_in[7];
    const float* bias     = (const float*)d_in[8];
    float* out = (float*)d_out;

    int N = in_sizes[0] / IN_F;
    int E = in_sizes[1] / 2;

    {
        int threads = N * 16;
        int grid = (threads + 255) / 256;
        node_kernel<<<grid, 256>>>(x, ln_gamma, ln_beta, root, bias,
                                   (const unsigned int*)eidx, out, N);
    }
    edge_kernel<<<(E + EB - 1) / EB, 256>>>(eidx, eattr, w_edge, b_edge, out, E);
}